// round 12
// baseline (speedup 1.0000x reference)
#include <cuda_runtime.h>
#include <cuda_fp16.h>
#include <cstdint>

#define B_ 2
#define S_ 2048
#define D_ 512
#define V_ 32000
#define H_ 11
#define HP 12           // padded H stride
#define R_ (B_*S_)      // 4096 rows
#define KCH 16          // attv k-chunks (128 keys each)

// GEMM tiling
#define LDP 40                          // padded row stride in fp16 halves (80 B)
#define ROWB (LDP * 2)                  // 80 bytes
#define TILE_A_BYTES (128 * ROWB)       // 10240
#define TILE_B_BYTES (256 * ROWB)       // 20480
#define NKC 16                          // K chunks of 32
#define MT_ (R_ / 128)                  // 32 row tiles
#define NT_ (V_ / 256)                  // 125 col tiles

// fp16 scaling (exact powers of 2)
#define A_SCALE 16.0f                   // 2^4
#define B_SCALE 64.0f                   // 2^6
#define OUT_SCALE (1.0f / 1024.0f)      // 2^-10

// ---------------- scratch (device globals: allocation-free, zero-init) ----------------
__device__ float g_emb[R_ * D_];
__device__ float g_h1 [R_ * D_];
__device__ float g_q  [R_ * HP];                     // pad lane h=11 stays 0
__device__ float g_k  [R_ * HP];
__device__ float g_v  [R_ * HP];
__device__ float g_att[(size_t)B_ * S_ * S_];        // attT[b][k][q]
__device__ float g_part[KCH * R_ * HP];              // att@v partials
__device__ float g_res [R_ * HP];                    // summed partials
__device__ float g_wt [2 * 33 * D_];                 // transposed qkv weights [ph][o][c]
__device__ float g_wb [2 * 33];                      // packed biases
// pre-tiled, pre-padded fp16 operand images (byte-exact smem tiles)
__device__ uint4 g_a_hi4[(size_t)MT_ * NKC * TILE_A_BYTES / 16];
__device__ uint4 g_bt_hi4[(size_t)NT_ * NKC * TILE_B_BYTES / 16];

// ---------------- 0) transpose qkv weights: W[c][h] -> Wt[o][c] ----------------
__global__ void prep_wt_kernel(const float* __restrict__ k1w, const float* __restrict__ q1w,
                               const float* __restrict__ v1w, const float* __restrict__ k2w,
                               const float* __restrict__ q2w, const float* __restrict__ v2w,
                               const float* __restrict__ k1b, const float* __restrict__ q1b,
                               const float* __restrict__ v1b, const float* __restrict__ k2b,
                               const float* __restrict__ q2b, const float* __restrict__ v2b) {
    const float* ws[6] = { k1w, q1w, v1w, k2w, q2w, v2w };
    const float* bs[6] = { k1b, q1b, v1b, k2b, q2b, v2b };
    int idx = blockIdx.x * 256 + threadIdx.x;        // [0, 2*33*512)
    if (idx < 2 * 33 * D_) {
        int ph = idx / (33 * D_);
        int rem = idx - ph * 33 * D_;
        int o = rem / D_, c = rem % D_;
        int mtx = ph * 3 + o / 11, h = o % 11;
        g_wt[idx] = ws[mtx][c * H_ + h];
    }
    if (idx < 66) {
        int ph = idx / 33, o = idx % 33;
        g_wb[idx] = bs[ph * 3 + o / 11][o % 11];
    }
}

// ---------------- 1) embedding + positional encoding ----------------
__global__ void embed_kernel(const int* __restrict__ x, const float* __restrict__ tab) {
    int idx = blockIdx.x * 256 + threadIdx.x;
    int d  = idx & (D_ - 1);
    int rs = idx >> 9;
    int s  = rs & (S_ - 1);
    int tok = x[rs];
    int e = d & ~1;
    float ang = (float)s * expf(-(float)e * (9.210340371976184f / 256.0f));
    float p = (d & 1) ? cosf(ang) : sinf(ang);
    g_emb[idx] = tab[(size_t)tok * D_ + d] + p;
}

// ---------------- 2) q/k/v projections (float4 dot with transposed W) ----------------
__global__ void qkv_kernel(int phase) {
    const float* src = phase ? g_h1 : g_emb;
    __shared__ float Esh[8 * D_];
    int r0 = blockIdx.x * 8;
    int tid = threadIdx.x;
    {
        const float4* s4 = (const float4*)(src + (size_t)r0 * D_);
        float4* e4 = (float4*)Esh;
        #pragma unroll
        for (int i = 0; i < 4; i++) e4[tid + i * 256] = s4[tid + i * 256];
    }
    __syncthreads();
    const float* wt = g_wt + phase * 33 * D_;
    const float* wb = g_wb + phase * 33;
    for (int t = tid; t < 8 * 33; t += 256) {
        int row = t / 33, o = t % 33;
        const float4* e4 = (const float4*)&Esh[row * D_];
        const float4* w4 = (const float4*)&wt[o * D_];
        float4 a = {0.f, 0.f, 0.f, 0.f};
        #pragma unroll 8
        for (int c = 0; c < D_ / 4; c++) {
            float4 ev = e4[c], wv = w4[c];
            a.x = fmaf(ev.x, wv.x, a.x);
            a.y = fmaf(ev.y, wv.y, a.y);
            a.z = fmaf(ev.z, wv.z, a.z);
            a.w = fmaf(ev.w, wv.w, a.w);
        }
        float sacc = (a.x + a.y) + (a.z + a.w) + wb[o];
        float* dst = (o < 11) ? g_k : (o < 22) ? g_q : g_v;
        dst[(r0 + row) * HP + (o % 11)] = sacc;
    }
}

// ---------------- 3) scores + causal mask + softmax over QUERY axis ----------------
// float4 Q loads (pad lane is zero), shuffle reductions.
__global__ void scores_kernel() {
    int k = blockIdx.x, b = blockIdx.y;
    int tid = threadIdx.x;
    __shared__ float4 kv4s[3];
    __shared__ float redm[8], reds[8];
    if (tid < 3) kv4s[tid] = ((const float4*)&g_k[(b * S_ + k) * HP])[tid];
    __syncthreads();
    float4 k0 = kv4s[0], k1 = kv4s[1], k2 = kv4s[2];

    float dloc[8];
    float m = -1e30f;
    int cnt = 0;
    for (int q = k + tid; q < S_; q += 256) {
        const float4* qp = (const float4*)&g_q[(b * S_ + q) * HP];
        float4 a = qp[0], bq = qp[1], cq = qp[2];
        float d = a.x * k0.x + a.y * k0.y + a.z * k0.z + a.w * k0.w
                + bq.x * k1.x + bq.y * k1.y + bq.z * k1.z + bq.w * k1.w
                + cq.x * k2.x + cq.y * k2.y + cq.z * k2.z + cq.w * k2.w;
        dloc[cnt++] = d;
        m = fmaxf(m, d);
    }
    #pragma unroll
    for (int o = 16; o > 0; o >>= 1) m = fmaxf(m, __shfl_xor_sync(0xFFFFFFFFu, m, o));
    if ((tid & 31) == 0) redm[tid >> 5] = m;
    __syncthreads();
    float M = fmaxf(fmaxf(fmaxf(redm[0], redm[1]), fmaxf(redm[2], redm[3])),
                    fmaxf(fmaxf(redm[4], redm[5]), fmaxf(redm[6], redm[7])));

    float ssum = 0.f;
    for (int i = 0; i < cnt; i++) { dloc[i] = expf(dloc[i] - M); ssum += dloc[i]; }
    #pragma unroll
    for (int o = 16; o > 0; o >>= 1) ssum += __shfl_xor_sync(0xFFFFFFFFu, ssum, o);
    if ((tid & 31) == 0) reds[tid >> 5] = ssum;
    __syncthreads();
    float inv = 1.0f / (((reds[0] + reds[1]) + (reds[2] + reds[3]))
                      + ((reds[4] + reds[5]) + (reds[6] + reds[7])));

    size_t rowbase = ((size_t)b * S_ + k) * S_;
    cnt = 0;
    for (int q = k + tid; q < S_; q += 256) g_att[rowbase + q] = dloc[cnt++] * inv;
    for (int q = tid; q < k; q += 256)      g_att[rowbase + q] = 0.f;
}

// ---------------- 4) res = att @ v  (16 k-chunks, causal early-out) ----------------
__global__ void attv_kernel() {
    int qt = blockIdx.x, kc = blockIdx.y, b = blockIdx.z;
    int tid = threadIdx.x;
    int q = qt * 128 + tid;
    float* dst = &g_part[((kc * R_) + b * S_ + q) * HP];
    if (kc > qt) {                       // fully masked chunk
        #pragma unroll
        for (int h = 0; h < H_; h++) dst[h] = 0.f;
        return;
    }
    __shared__ float vsh[128 * HP];
    int k0 = kc * 128;
    const float* vbase = &g_v[(b * S_ + k0) * HP];
    for (int i = tid; i < 128 * HP; i += 128) vsh[i] = vbase[i];
    __syncthreads();

    float acc[H_];
    #pragma unroll
    for (int h = 0; h < H_; h++) acc[h] = 0.f;

    size_t attbase = ((size_t)b * S_ + k0) * S_ + q;
    for (int kk = 0; kk < 128; kk++) {
        float a = g_att[attbase + (size_t)kk * S_];
        const float* vr = &vsh[kk * HP];
        #pragma unroll
        for (int h = 0; h < H_; h++) acc[h] += a * vr[h];
    }
    #pragma unroll
    for (int h = 0; h < H_; h++) dst[h] = acc[h];
}

// ---------------- 4b) sum partials ----------------
__global__ void reduce_part_kernel() {
    int idx = blockIdx.x * 256 + threadIdx.x;        // [0, R_*HP)
    float s = 0.f;
    #pragma unroll
    for (int p = 0; p < KCH; p++) s += g_part[p * R_ * HP + idx];
    g_res[idx] = s;
}

// ---------------- 5) out = res @ fw + fb ----------------
// phase 0: fp32 to g_h1. phase 1: fp16 (x A_SCALE) into tiled GEMM-A layout.
__global__ void ff_kernel(int phase, const float* __restrict__ fw, const float* __restrict__ fb) {
    int idx = blockIdx.x * 256 + threadIdx.x;
    int r = idx >> 9, d = idx & (D_ - 1);
    float sacc = fb[d];
    #pragma unroll
    for (int h = 0; h < H_; h++) sacc += g_res[r * HP + h] * fw[h * D_ + d];
    if (phase == 0) {
        g_h1[idx] = sacc;
    } else {
        int mt = r >> 7, rrow = r & 127, kc = d >> 5, kk = d & 31;
        size_t off = (((size_t)(mt * NKC + kc) * 128) + rrow) * LDP + kk;
        ((__half*)g_a_hi4)[off] = __float2half(sacc * A_SCALE);
    }
}

// ---------------- 6a) transpose out_w -> tiled fp16 GEMM-B layout ----------------
__global__ void conv_b_kernel(const float* __restrict__ outw) {
    __shared__ float t[32][33];
    int v0 = blockIdx.x * 32, k0 = blockIdx.y * 32;
    int tx = threadIdx.x, ty = threadIdx.y;          // 32 x 8
    #pragma unroll
    for (int j = 0; j < 4; j++) {
        int k = k0 + ty + j * 8;
        t[ty + j * 8][tx] = outw[(size_t)k * V_ + v0 + tx];
    }
    __syncthreads();
    int kc = k0 >> 5;
    #pragma unroll
    for (int j = 0; j < 4; j++) {
        int v = v0 + ty + j * 8;
        float val = t[tx][ty + j * 8] * B_SCALE;     // = outw[k0+tx][v] * 2^6
        int nt = v >> 8, vrow = v & 255;
        size_t off = (((size_t)(nt * NKC + kc) * 256) + vrow) * LDP + tx;
        ((__half*)g_bt_hi4)[off] = __float2half(val);
    }
}

// ---------------- 6b) bulk-copy pipelined fp16 MMA GEMM ----------------
// Tile 128x256, K-chunk 32, 4-stage cp.async.bulk + mbarrier pipeline.
// C = (Ah*Bh) * 2^-10 + bias;  dropped Al*Bh + Ah*Bl ~ 3e-4 relative.
#define B_HI_O TILE_A_BYTES                  // 10240
#define STG_SZ (TILE_A_BYTES + TILE_B_BYTES) // 30720
#define NSTAGE 4
#define CTRL 1024
#define GSMEM (CTRL + NSTAGE * STG_SZ)       // 123904

__device__ __forceinline__ uint32_t smem_u32(const void* p) {
    uint32_t r;
    asm("{ .reg .u64 t; cvta.to.shared.u64 t, %1; cvt.u32.u64 %0, t; }"
        : "=r"(r) : "l"(p));
    return r;
}
__device__ __forceinline__ void bulk_g2s(uint32_t dst, const void* src, uint32_t bytes,
                                         uint32_t mbar) {
    asm volatile(
        "cp.async.bulk.shared::cluster.global.mbarrier::complete_tx::bytes [%0], [%1], %2, [%3];"
        :: "r"(dst), "l"(src), "r"(bytes), "r"(mbar) : "memory");
}
__device__ __forceinline__ void mbar_expect(uint32_t mbar, uint32_t bytes) {
    asm volatile("mbarrier.arrive.expect_tx.shared.b64 _, [%0], %1;"
                 :: "r"(mbar), "r"(bytes) : "memory");
}
__device__ __forceinline__ void mbar_wait(uint32_t addr, uint32_t parity) {
    asm volatile(
        "{\n\t.reg .pred P;\n\t"
        "W_%=:\n\t"
        "mbarrier.try_wait.parity.acquire.cta.shared::cta.b64 P, [%0], %1, 0x989680;\n\t"
        "@P bra.uni D_%=;\n\t"
        "bra.uni W_%=;\n\t"
        "D_%=:\n\t}"
        :: "r"(addr), "r"(parity) : "memory");
}
__device__ __forceinline__ void ldmatrix4(uint32_t* r, uint32_t addr) {
    asm volatile("ldmatrix.sync.aligned.m8n8.x4.shared.b16 {%0,%1,%2,%3}, [%4];"
                 : "=r"(r[0]), "=r"(r[1]), "=r"(r[2]), "=r"(r[3]) : "r"(addr));
}
__device__ __forceinline__ void mma16816(float* c, const uint32_t* a, uint32_t b0, uint32_t b1) {
    asm volatile(
        "mma.sync.aligned.m16n8k16.row.col.f32.f16.f16.f32 "
        "{%0,%1,%2,%3}, {%4,%5,%6,%7}, {%8,%9}, {%0,%1,%2,%3};"
        : "+f"(c[0]), "+f"(c[1]), "+f"(c[2]), "+f"(c[3])
        : "r"(a[0]), "r"(a[1]), "r"(a[2]), "r"(a[3]), "r"(b0), "r"(b1));
}

__global__ __launch_bounds__(256, 1)
void gemm_mma_kernel(const float* __restrict__ bias, float* __restrict__ C) {
    extern __shared__ __align__(16) char smem[];
    uint32_t sb = smem_u32(smem);
    int tid = threadIdx.x;
    int wid = tid >> 5, lid = tid & 31;
    int rowBase = blockIdx.x * 128;
    int colBase = blockIdx.y * 256;

    const char* gAh = (const char*)g_a_hi4 + (size_t)blockIdx.x * NKC * TILE_A_BYTES;
    const char* gBh = (const char*)g_bt_hi4 + (size_t)blockIdx.y * NKC * TILE_B_BYTES;

    if (tid == 0) {
        #pragma unroll
        for (int s = 0; s < NSTAGE; s++)
            asm volatile("mbarrier.init.shared.b64 [%0], 1;" :: "r"(sb + 8u * s) : "memory");
    }
    __syncthreads();

    auto issue = [&](int c, int s) {
        uint32_t mb = sb + 8u * s;
        uint32_t stg = sb + CTRL + (uint32_t)s * STG_SZ;
        mbar_expect(mb, STG_SZ);
        bulk_g2s(stg, gAh + (size_t)c * TILE_A_BYTES, TILE_A_BYTES, mb);
        bulk_g2s(stg + B_HI_O,                    gBh + (size_t)c * TILE_B_BYTES, TILE_B_BYTES / 2, mb);
        bulk_g2s(stg + B_HI_O + TILE_B_BYTES / 2, gBh + (size_t)c * TILE_B_BYTES + TILE_B_BYTES / 2, TILE_B_BYTES / 2, mb);
    };

    if (tid == 0) { issue(0, 0); issue(1, 1); issue(2, 2); issue(3, 3); }

    int warpM = (wid & 1) * 64;       // 2 m-warps
    int warpN = (wid >> 1) * 64;      // 4 n-warps
    int lrow = lid & 15;
    int lk = (lid >> 4) * 8;

    float acc[4][8][4];
    #pragma unroll
    for (int i = 0; i < 4; i++)
        #pragma unroll
        for (int j = 0; j < 8; j++)
            #pragma unroll
            for (int v = 0; v < 4; v++) acc[i][j][v] = 0.f;

    #pragma unroll 1
    for (int c = 0; c < NKC; c++) {
        int s = c % NSTAGE;
        mbar_wait(sb + 8u * s, (c / NSTAGE) & 1);
        uint32_t stg = sb + CTRL + (uint32_t)s * STG_SZ;

        #pragma unroll
        for (int k16 = 0; k16 < 2; k16++) {
            uint32_t a[4][4];
            #pragma unroll
            for (int mi = 0; mi < 4; mi++)
                ldmatrix4(a[mi], stg + ((warpM + mi * 16 + lrow) * LDP + k16 * 16 + lk) * 2);
            uint32_t b[4][4];
            #pragma unroll
            for (int ni = 0; ni < 4; ni++)
                ldmatrix4(b[ni], stg + B_HI_O + ((warpN + ni * 16 + lrow) * LDP + k16 * 16 + lk) * 2);
            #pragma unroll
            for (int mi = 0; mi < 4; mi++)
                #pragma unroll
                for (int nj = 0; nj < 8; nj++) {
                    uint32_t b0 = (nj & 1) ? b[nj >> 1][1] : b[nj >> 1][0];
                    uint32_t b1 = (nj & 1) ? b[nj >> 1][3] : b[nj >> 1][2];
                    mma16816(acc[mi][nj], a[mi], b0, b1);
                }
        }
        __syncthreads();
        if (tid == 0 && c + NSTAGE < NKC) issue(c + NSTAGE, s);
    }

    // ---- epilogue: unscale + bias, direct stores ----
    int g = lid >> 2, tig = lid & 3;
    #pragma unroll
    for (int mi = 0; mi < 4; mi++) {
        #pragma unroll
        for (int nj = 0; nj < 8; nj++) {
            int row = rowBase + warpM + mi * 16 + g;
            int col = colBase + warpN + nj * 8 + tig * 2;
            float2 bv = *(const float2*)&bias[col];
            float2 o0 = { acc[mi][nj][0] * OUT_SCALE + bv.x, acc[mi][nj][1] * OUT_SCALE + bv.y };
            float2 o1 = { acc[mi][nj][2] * OUT_SCALE + bv.x, acc[mi][nj][3] * OUT_SCALE + bv.y };
            *(float2*)&C[(size_t)row * V_ + col] = o0;
            *(float2*)&C[(size_t)(row + 8) * V_ + col] = o1;
        }
    }
}

// ---------------- launch ----------------
extern "C" void kernel_launch(void* const* d_in, const int* in_sizes, int n_in,
                              void* d_out, int out_size) {
    const int*   x    = (const int*)d_in[0];
    const float* tab  = (const float*)d_in[1];
    const float* k1w  = (const float*)d_in[2];
    const float* k1b  = (const float*)d_in[3];
    const float* q1w  = (const float*)d_in[4];
    const float* q1b  = (const float*)d_in[5];
    const float* v1w  = (const float*)d_in[6];
    const float* v1b  = (const float*)d_in[7];
    const float* f1w  = (const float*)d_in[8];
    const float* f1b  = (const float*)d_in[9];
    const float* k2w  = (const float*)d_in[10];
    const float* k2b  = (const float*)d_in[11];
    const float* q2w  = (const float*)d_in[12];
    const float* q2b  = (const float*)d_in[13];
    const float* v2w  = (const float*)d_in[14];
    const float* v2b  = (const float*)d_in[15];
    const float* f2w  = (const float*)d_in[16];
    const float* f2b  = (const float*)d_in[17];
    const float* outw = (const float*)d_in[18];
    const float* outb = (const float*)d_in[19];
    float* out = (float*)d_out;

    cudaFuncSetAttribute(gemm_mma_kernel, cudaFuncAttributeMaxDynamicSharedMemorySize, GSMEM);

    // weight prep (independent of activations)
    prep_wt_kernel<<<(2 * 33 * D_ + 255) / 256, 256>>>(k1w, q1w, v1w, k2w, q2w, v2w,
                                                        k1b, q1b, v1b, k2b, q2b, v2b);
    conv_b_kernel<<<dim3(V_ / 32, D_ / 32), dim3(32, 8)>>>(outw);

    embed_kernel<<<(R_ * D_) / 256, 256>>>(x, tab);

    // attention block 1: g_emb -> g_h1
    qkv_kernel<<<R_ / 8, 256>>>(0);
    scores_kernel<<<dim3(S_, B_), 256>>>();
    attv_kernel<<<dim3(16, KCH, 2), 128>>>();
    reduce_part_kernel<<<(R_ * HP) / 256, 256>>>();
    ff_kernel<<<(R_ * D_) / 256, 256>>>(0, f1w, f1b);

    // attention block 2: g_h1 -> tiled fp16 (fused in ff phase 1)
    qkv_kernel<<<R_ / 8, 256>>>(1);
    scores_kernel<<<dim3(S_, B_), 256>>>();
    attv_kernel<<<dim3(16, KCH, 2), 128>>>();
    reduce_part_kernel<<<(R_ * HP) / 256, 256>>>();
    ff_kernel<<<(R_ * D_) / 256, 256>>>(1, f2w, f2b);

    // final vocab projection: bulk-fed fp16 tensor-core GEMM
    gemm_mma_kernel<<<dim3(MT_, NT_), 256, GSMEM>>>(outb, out);
}

// round 14
// speedup vs baseline: 1.7353x; 1.7353x over previous
#include <cuda_runtime.h>
#include <cuda_fp16.h>
#include <cstdint>

#define B_ 2
#define S_ 2048
#define D_ 512
#define V_ 32000
#define H_ 11
#define HP 12           // padded H stride
#define R_ (B_*S_)      // 4096 rows
#define KCH 16          // attv k-chunks (128 keys each)

// GEMM tiling
#define LDP 40                          // padded row stride in fp16 halves (80 B)
#define ROWB (LDP * 2)                  // 80 bytes
#define TILE_A_BYTES (128 * ROWB)       // 10240
#define TILE_B_BYTES (256 * ROWB)       // 20480
#define NKC 16                          // K chunks of 32
#define MT_ (R_ / 128)                  // 32 row tiles
#define NT_ (V_ / 256)                  // 125 col tiles

// fp16 scaling (exact powers of 2)
#define A_SCALE 16.0f                   // 2^4
#define B_SCALE 64.0f                   // 2^6
#define OUT_SCALE (1.0f / 1024.0f)      // 2^-10

// ---------------- scratch (device globals: allocation-free, zero-init) ----------------
__device__ float g_emb[R_ * D_];
__device__ float g_h1 [R_ * D_];
__device__ float g_q  [R_ * HP];
__device__ float g_k  [R_ * HP];
__device__ float g_v  [R_ * HP];
__device__ float g_att[(size_t)B_ * S_ * S_];        // attT[b][k][q]
__device__ float g_part[KCH * R_ * HP];              // att@v partials
__device__ float g_res [R_ * HP];                    // summed partials
__device__ float g_wt [2 * 33 * D_];                 // transposed qkv weights [ph][o][c]
__device__ float g_wb [2 * 33];                      // packed biases
// pre-tiled, pre-padded fp16 operand images (byte-exact smem tiles)
__device__ uint4 g_a_hi4[(size_t)MT_ * NKC * TILE_A_BYTES / 16];
__device__ uint4 g_bt_hi4[(size_t)NT_ * NKC * TILE_B_BYTES / 16];

// ---------------- 0) transpose qkv weights: W[c][h] -> Wt[o][c] ----------------
__global__ void prep_wt_kernel(const float* __restrict__ k1w, const float* __restrict__ q1w,
                               const float* __restrict__ v1w, const float* __restrict__ k2w,
                               const float* __restrict__ q2w, const float* __restrict__ v2w,
                               const float* __restrict__ k1b, const float* __restrict__ q1b,
                               const float* __restrict__ v1b, const float* __restrict__ k2b,
                               const float* __restrict__ q2b, const float* __restrict__ v2b) {
    const float* ws[6] = { k1w, q1w, v1w, k2w, q2w, v2w };
    const float* bs[6] = { k1b, q1b, v1b, k2b, q2b, v2b };
    int idx = blockIdx.x * 256 + threadIdx.x;        // [0, 2*33*512)
    if (idx < 2 * 33 * D_) {
        int ph = idx / (33 * D_);
        int rem = idx - ph * 33 * D_;
        int o = rem / D_, c = rem % D_;
        int mtx = ph * 3 + o / 11, h = o % 11;
        g_wt[idx] = ws[mtx][c * H_ + h];
    }
    if (idx < 66) {
        int ph = idx / 33, o = idx % 33;
        g_wb[idx] = bs[ph * 3 + o / 11][o % 11];
    }
}

// ---------------- 1) embedding + positional encoding ----------------
__global__ void embed_kernel(const int* __restrict__ x, const float* __restrict__ tab) {
    int idx = blockIdx.x * 256 + threadIdx.x;
    int d  = idx & (D_ - 1);
    int rs = idx >> 9;
    int s  = rs & (S_ - 1);
    int tok = x[rs];
    int e = d & ~1;
    float ang = (float)s * expf(-(float)e * (9.210340371976184f / 256.0f));
    float p = (d & 1) ? cosf(ang) : sinf(ang);
    g_emb[idx] = tab[(size_t)tok * D_ + d] + p;
}

// ---------------- 2) q/k/v projections: warp-per-row, coalesced Wt reads ----------------
__global__ void qkv_kernel(int phase) {
    const float* src = phase ? g_h1 : g_emb;
    __shared__ float Esh[8 * D_];
    int r0 = blockIdx.x * 8;
    int tid = threadIdx.x;
    {
        const float4* s4 = (const float4*)(src + (size_t)r0 * D_);
        float4* e4 = (float4*)Esh;
        #pragma unroll
        for (int i = 0; i < 4; i++) e4[tid + i * 256] = s4[tid + i * 256];
    }
    __syncthreads();

    int w = tid >> 5, lane = tid & 31;               // warp = row
    // lane-resident slice of this row: float4 at (lane + 32*j), conflict-free LDS
    float4 e[4];
    #pragma unroll
    for (int j = 0; j < 4; j++) e[j] = ((const float4*)&Esh[w * D_])[lane + 32 * j];

    const float* wt = g_wt + phase * 33 * D_;
    const float* wb = g_wb + phase * 33;
    int row = r0 + w;
    #pragma unroll 3
    for (int o = 0; o < 33; o++) {
        const float4* w4 = (const float4*)&wt[o * D_];
        float s = 0.f;
        #pragma unroll
        for (int j = 0; j < 4; j++) {
            float4 wv = w4[lane + 32 * j];           // coalesced 128B per j
            s += e[j].x * wv.x + e[j].y * wv.y + e[j].z * wv.z + e[j].w * wv.w;
        }
        #pragma unroll
        for (int off = 16; off > 0; off >>= 1) s += __shfl_xor_sync(0xFFFFFFFFu, s, off);
        if (lane == 0) {
            float* dst = (o < 11) ? g_k : (o < 22) ? g_q : g_v;
            dst[row * HP + (o % 11)] = s + wb[o];
        }
    }
}

// ---------------- 3) scores + causal mask + softmax over QUERY axis (R11 version) ----
__global__ void scores_kernel() {
    int k = blockIdx.x, b = blockIdx.y;
    int tid = threadIdx.x;
    __shared__ float kv[H_];
    __shared__ float red[256];
    if (tid < H_) kv[tid] = g_k[(b * S_ + k) * HP + tid];
    __syncthreads();

    float dloc[8];
    float m = -1e30f;
    int cnt = 0;
    for (int q = k + tid; q < S_; q += 256) {
        const float* qp = &g_q[(b * S_ + q) * HP];
        float d = 0.f;
        #pragma unroll
        for (int h = 0; h < H_; h++) d += qp[h] * kv[h];
        dloc[cnt++] = d;
        m = fmaxf(m, d);
    }
    red[tid] = m; __syncthreads();
    #pragma unroll
    for (int s = 128; s > 0; s >>= 1) {
        if (tid < s) red[tid] = fmaxf(red[tid], red[tid + s]);
        __syncthreads();
    }
    float M = red[0]; __syncthreads();

    float ssum = 0.f;
    for (int i = 0; i < cnt; i++) { dloc[i] = expf(dloc[i] - M); ssum += dloc[i]; }
    red[tid] = ssum; __syncthreads();
    #pragma unroll
    for (int s = 128; s > 0; s >>= 1) {
        if (tid < s) red[tid] += red[tid + s];
        __syncthreads();
    }
    float inv = 1.0f / red[0];

    size_t rowbase = ((size_t)b * S_ + k) * S_;
    cnt = 0;
    for (int q = k + tid; q < S_; q += 256) g_att[rowbase + q] = dloc[cnt++] * inv;
    for (int q = tid; q < k; q += 256)      g_att[rowbase + q] = 0.f;
}

// ---------------- 4) res = att @ v  (16 k-chunks, causal early-out) ----------------
__global__ void attv_kernel() {
    int qt = blockIdx.x, kc = blockIdx.y, b = blockIdx.z;
    int tid = threadIdx.x;
    int q = qt * 128 + tid;
    float* dst = &g_part[((kc * R_) + b * S_ + q) * HP];
    if (kc > qt) {                       // fully masked chunk
        #pragma unroll
        for (int h = 0; h < H_; h++) dst[h] = 0.f;
        return;
    }
    __shared__ float vsh[128 * HP];
    int k0 = kc * 128;
    const float* vbase = &g_v[(b * S_ + k0) * HP];
    for (int i = tid; i < 128 * HP; i += 128) vsh[i] = vbase[i];
    __syncthreads();

    float acc[H_];
    #pragma unroll
    for (int h = 0; h < H_; h++) acc[h] = 0.f;

    size_t attbase = ((size_t)b * S_ + k0) * S_ + q;
    for (int kk = 0; kk < 128; kk++) {
        float a = g_att[attbase + (size_t)kk * S_];
        const float* vr = &vsh[kk * HP];
        #pragma unroll
        for (int h = 0; h < H_; h++) acc[h] += a * vr[h];
    }
    #pragma unroll
    for (int h = 0; h < H_; h++) dst[h] = acc[h];
}

// ---------------- 4b) sum partials ----------------
__global__ void reduce_part_kernel() {
    int idx = blockIdx.x * 256 + threadIdx.x;        // [0, R_*HP)
    float s = 0.f;
    #pragma unroll
    for (int p = 0; p < KCH; p++) s += g_part[p * R_ * HP + idx];
    g_res[idx] = s;
}

// ---------------- 5) out = res @ fw + fb ----------------
// phase 0: fp32 to g_h1. phase 1: fp16 (x A_SCALE) into tiled GEMM-A layout.
__global__ void ff_kernel(int phase, const float* __restrict__ fw, const float* __restrict__ fb) {
    int idx = blockIdx.x * 256 + threadIdx.x;
    int r = idx >> 9, d = idx & (D_ - 1);
    float sacc = fb[d];
    #pragma unroll
    for (int h = 0; h < H_; h++) sacc += g_res[r * HP + h] * fw[h * D_ + d];
    if (phase == 0) {
        g_h1[idx] = sacc;
    } else {
        int mt = r >> 7, rrow = r & 127, kc = d >> 5, kk = d & 31;
        size_t off = (((size_t)(mt * NKC + kc) * 128) + rrow) * LDP + kk;
        ((__half*)g_a_hi4)[off] = __float2half(sacc * A_SCALE);
    }
}

// ---------------- 6a) transpose out_w -> tiled fp16 GEMM-B layout ----------------
__global__ void conv_b_kernel(const float* __restrict__ outw) {
    __shared__ float t[32][33];
    int v0 = blockIdx.x * 32, k0 = blockIdx.y * 32;
    int tx = threadIdx.x, ty = threadIdx.y;          // 32 x 8
    #pragma unroll
    for (int j = 0; j < 4; j++) {
        int k = k0 + ty + j * 8;
        t[ty + j * 8][tx] = outw[(size_t)k * V_ + v0 + tx];
    }
    __syncthreads();
    int kc = k0 >> 5;
    #pragma unroll
    for (int j = 0; j < 4; j++) {
        int v = v0 + ty + j * 8;
        float val = t[tx][ty + j * 8] * B_SCALE;     // = outw[k0+tx][v] * 2^6
        int nt = v >> 8, vrow = v & 255;
        size_t off = (((size_t)(nt * NKC + kc) * 256) + vrow) * LDP + tx;
        ((__half*)g_bt_hi4)[off] = __float2half(val);
    }
}

// ---------------- 6b) bulk-copy pipelined fp16 MMA GEMM ----------------
#define B_HI_O TILE_A_BYTES                  // 10240
#define STG_SZ (TILE_A_BYTES + TILE_B_BYTES) // 30720
#define NSTAGE 4
#define CTRL 1024
#define GSMEM (CTRL + NSTAGE * STG_SZ)       // 123904

__device__ __forceinline__ uint32_t smem_u32(const void* p) {
    uint32_t r;
    asm("{ .reg .u64 t; cvta.to.shared.u64 t, %1; cvt.u32.u64 %0, t; }"
        : "=r"(r) : "l"(p));
    return r;
}
__device__ __forceinline__ void bulk_g2s(uint32_t dst, const void* src, uint32_t bytes,
                                         uint32_t mbar) {
    asm volatile(
        "cp.async.bulk.shared::cluster.global.mbarrier::complete_tx::bytes [%0], [%1], %2, [%3];"
        :: "r"(dst), "l"(src), "r"(bytes), "r"(mbar) : "memory");
}
__device__ __forceinline__ void mbar_expect(uint32_t mbar, uint32_t bytes) {
    asm volatile("mbarrier.arrive.expect_tx.shared.b64 _, [%0], %1;"
                 :: "r"(mbar), "r"(bytes) : "memory");
}
__device__ __forceinline__ void mbar_wait(uint32_t addr, uint32_t parity) {
    asm volatile(
        "{\n\t.reg .pred P;\n\t"
        "W_%=:\n\t"
        "mbarrier.try_wait.parity.acquire.cta.shared::cta.b64 P, [%0], %1, 0x989680;\n\t"
        "@P bra.uni D_%=;\n\t"
        "bra.uni W_%=;\n\t"
        "D_%=:\n\t}"
        :: "r"(addr), "r"(parity) : "memory");
}
__device__ __forceinline__ void ldmatrix4(uint32_t* r, uint32_t addr) {
    asm volatile("ldmatrix.sync.aligned.m8n8.x4.shared.b16 {%0,%1,%2,%3}, [%4];"
                 : "=r"(r[0]), "=r"(r[1]), "=r"(r[2]), "=r"(r[3]) : "r"(addr));
}
__device__ __forceinline__ void mma16816(float* c, const uint32_t* a, uint32_t b0, uint32_t b1) {
    asm volatile(
        "mma.sync.aligned.m16n8k16.row.col.f32.f16.f16.f32 "
        "{%0,%1,%2,%3}, {%4,%5,%6,%7}, {%8,%9}, {%0,%1,%2,%3};"
        : "+f"(c[0]), "+f"(c[1]), "+f"(c[2]), "+f"(c[3])
        : "r"(a[0]), "r"(a[1]), "r"(a[2]), "r"(a[3]), "r"(b0), "r"(b1));
}

__global__ __launch_bounds__(256, 1)
void gemm_mma_kernel(const float* __restrict__ bias, float* __restrict__ C) {
    extern __shared__ __align__(16) char smem[];
    uint32_t sb = smem_u32(smem);
    int tid = threadIdx.x;
    int wid = tid >> 5, lid = tid & 31;
    int rowBase = blockIdx.x * 128;
    int colBase = blockIdx.y * 256;

    const char* gAh = (const char*)g_a_hi4 + (size_t)blockIdx.x * NKC * TILE_A_BYTES;
    const char* gBh = (const char*)g_bt_hi4 + (size_t)blockIdx.y * NKC * TILE_B_BYTES;

    if (tid == 0) {
        #pragma unroll
        for (int s = 0; s < NSTAGE; s++)
            asm volatile("mbarrier.init.shared.b64 [%0], 1;" :: "r"(sb + 8u * s) : "memory");
    }
    __syncthreads();

    auto issue = [&](int c, int s) {
        uint32_t mb = sb + 8u * s;
        uint32_t stg = sb + CTRL + (uint32_t)s * STG_SZ;
        mbar_expect(mb, STG_SZ);
        bulk_g2s(stg, gAh + (size_t)c * TILE_A_BYTES, TILE_A_BYTES, mb);
        bulk_g2s(stg + B_HI_O,                    gBh + (size_t)c * TILE_B_BYTES, TILE_B_BYTES / 2, mb);
        bulk_g2s(stg + B_HI_O + TILE_B_BYTES / 2, gBh + (size_t)c * TILE_B_BYTES + TILE_B_BYTES / 2, TILE_B_BYTES / 2, mb);
    };

    if (tid == 0) { issue(0, 0); issue(1, 1); issue(2, 2); issue(3, 3); }

    int warpM = (wid & 1) * 64;       // 2 m-warps
    int warpN = (wid >> 1) * 64;      // 4 n-warps
    int lrow = lid & 15;
    int lk = (lid >> 4) * 8;

    float acc[4][8][4];
    #pragma unroll
    for (int i = 0; i < 4; i++)
        #pragma unroll
        for (int j = 0; j < 8; j++)
            #pragma unroll
            for (int v = 0; v < 4; v++) acc[i][j][v] = 0.f;

    #pragma unroll 1
    for (int c = 0; c < NKC; c++) {
        int s = c % NSTAGE;
        mbar_wait(sb + 8u * s, (c / NSTAGE) & 1);
        uint32_t stg = sb + CTRL + (uint32_t)s * STG_SZ;

        #pragma unroll
        for (int k16 = 0; k16 < 2; k16++) {
            uint32_t a[4][4];
            #pragma unroll
            for (int mi = 0; mi < 4; mi++)
                ldmatrix4(a[mi], stg + ((warpM + mi * 16 + lrow) * LDP + k16 * 16 + lk) * 2);
            uint32_t b[4][4];
            #pragma unroll
            for (int ni = 0; ni < 4; ni++)
                ldmatrix4(b[ni], stg + B_HI_O + ((warpN + ni * 16 + lrow) * LDP + k16 * 16 + lk) * 2);
            #pragma unroll
            for (int mi = 0; mi < 4; mi++)
                #pragma unroll
                for (int nj = 0; nj < 8; nj++) {
                    uint32_t b0 = (nj & 1) ? b[nj >> 1][1] : b[nj >> 1][0];
                    uint32_t b1 = (nj & 1) ? b[nj >> 1][3] : b[nj >> 1][2];
                    mma16816(acc[mi][nj], a[mi], b0, b1);
                }
        }
        __syncthreads();
        if (tid == 0 && c + NSTAGE < NKC) issue(c + NSTAGE, s);
    }

    // ---- epilogue: unscale + bias, direct stores ----
    int g = lid >> 2, tig = lid & 3;
    #pragma unroll
    for (int mi = 0; mi < 4; mi++) {
        #pragma unroll
        for (int nj = 0; nj < 8; nj++) {
            int row = rowBase + warpM + mi * 16 + g;
            int col = colBase + warpN + nj * 8 + tig * 2;
            float2 bv = *(const float2*)&bias[col];
            float2 o0 = { acc[mi][nj][0] * OUT_SCALE + bv.x, acc[mi][nj][1] * OUT_SCALE + bv.y };
            float2 o1 = { acc[mi][nj][2] * OUT_SCALE + bv.x, acc[mi][nj][3] * OUT_SCALE + bv.y };
            *(float2*)&C[(size_t)row * V_ + col] = o0;
            *(float2*)&C[(size_t)(row + 8) * V_ + col] = o1;
        }
    }
}

// ---------------- launch ----------------
extern "C" void kernel_launch(void* const* d_in, const int* in_sizes, int n_in,
                              void* d_out, int out_size) {
    const int*   x    = (const int*)d_in[0];
    const float* tab  = (const float*)d_in[1];
    const float* k1w  = (const float*)d_in[2];
    const float* k1b  = (const float*)d_in[3];
    const float* q1w  = (const float*)d_in[4];
    const float* q1b  = (const float*)d_in[5];
    const float* v1w  = (const float*)d_in[6];
    const float* v1b  = (const float*)d_in[7];
    const float* f1w  = (const float*)d_in[8];
    const float* f1b  = (const float*)d_in[9];
    const float* k2w  = (const float*)d_in[10];
    const float* k2b  = (const float*)d_in[11];
    const float* q2w  = (const float*)d_in[12];
    const float* q2b  = (const float*)d_in[13];
    const float* v2w  = (const float*)d_in[14];
    const float* v2b  = (const float*)d_in[15];
    const float* f2w  = (const float*)d_in[16];
    const float* f2b  = (const float*)d_in[17];
    const float* outw = (const float*)d_in[18];
    const float* outb = (const float*)d_in[19];
    float* out = (float*)d_out;

    cudaFuncSetAttribute(gemm_mma_kernel, cudaFuncAttributeMaxDynamicSharedMemorySize, GSMEM);

    // weight prep (independent of activations)
    prep_wt_kernel<<<(2 * 33 * D_ + 255) / 256, 256>>>(k1w, q1w, v1w, k2w, q2w, v2w,
                                                        k1b, q1b, v1b, k2b, q2b, v2b);
    conv_b_kernel<<<dim3(V_ / 32, D_ / 32), dim3(32, 8)>>>(outw);

    embed_kernel<<<(R_ * D_) / 256, 256>>>(x, tab);

    // attention block 1: g_emb -> g_h1
    qkv_kernel<<<R_ / 8, 256>>>(0);
    scores_kernel<<<dim3(S_, B_), 256>>>();
    attv_kernel<<<dim3(16, KCH, 2), 128>>>();
    reduce_part_kernel<<<(R_ * HP) / 256, 256>>>();
    ff_kernel<<<(R_ * D_) / 256, 256>>>(0, f1w, f1b);

    // attention block 2: g_h1 -> tiled fp16 (fused in ff phase 1)
    qkv_kernel<<<R_ / 8, 256>>>(1);
    scores_kernel<<<dim3(S_, B_), 256>>>();
    attv_kernel<<<dim3(16, KCH, 2), 128>>>();
    reduce_part_kernel<<<(R_ * HP) / 256, 256>>>();
    ff_kernel<<<(R_ * D_) / 256, 256>>>(1, f2w, f2b);

    // final vocab projection: bulk-fed fp16 tensor-core GEMM
    gemm_mma_kernel<<<dim3(MT_, NT_), 256, GSMEM>>>(outb, out);
}

// round 17
// speedup vs baseline: 1.7985x; 1.0365x over previous
#include <cuda_runtime.h>
#include <cuda_fp16.h>
#include <cstdint>

#define B_ 2
#define S_ 2048
#define D_ 512
#define V_ 32000
#define H_ 11
#define HP 12           // padded H stride
#define R_ (B_*S_)      // 4096 rows
#define KCH 16          // attv k-chunks (128 keys each)

// GEMM tiling
#define LDP 40                          // padded row stride in fp16 halves (80 B)
#define ROWB (LDP * 2)                  // 80 bytes
#define TILE_A_BYTES (128 * ROWB)       // 10240
#define TILE_B_BYTES (256 * ROWB)       // 20480
#define NKC 16                          // K chunks of 32
#define MT_ (R_ / 128)                  // 32 row tiles
#define NT_ (V_ / 256)                  // 125 col tiles

// fp16 scaling (exact powers of 2)
#define A_SCALE 16.0f                   // 2^4
#define B_SCALE 64.0f                   // 2^6
#define OUT_SCALE (1.0f / 1024.0f)      // 2^-10

// ---------------- scratch (device globals: allocation-free, zero-init) ----------------
// NOTE: pad lane h=11 of g_q/g_k/g_v is never written -> stays 0 (enables float4 math)
__device__ float g_emb[R_ * D_];
__device__ float g_h1 [R_ * D_];
__device__ float g_q  [R_ * HP];
__device__ float g_k  [R_ * HP];
__device__ float g_v  [R_ * HP];
__device__ float g_att[(size_t)B_ * S_ * S_];        // attT[b][k][q]
__device__ float g_part[KCH * R_ * HP];              // att@v partials
__device__ float g_res [R_ * HP];                    // summed partials
__device__ float g_wt [2 * 33 * D_];                 // transposed qkv weights [ph][o][c]
__device__ float g_wb [2 * 33];                      // packed biases
// pre-tiled, pre-padded fp16 operand images (byte-exact smem tiles)
__device__ uint4 g_a_hi4[(size_t)MT_ * NKC * TILE_A_BYTES / 16];
__device__ uint4 g_bt_hi4[(size_t)NT_ * NKC * TILE_B_BYTES / 16];

// ---------------- 0) transpose qkv weights: W[c][h] -> Wt[o][c] ----------------
__global__ void prep_wt_kernel(const float* __restrict__ k1w, const float* __restrict__ q1w,
                               const float* __restrict__ v1w, const float* __restrict__ k2w,
                               const float* __restrict__ q2w, const float* __restrict__ v2w,
                               const float* __restrict__ k1b, const float* __restrict__ q1b,
                               const float* __restrict__ v1b, const float* __restrict__ k2b,
                               const float* __restrict__ q2b, const float* __restrict__ v2b) {
    const float* ws[6] = { k1w, q1w, v1w, k2w, q2w, v2w };
    const float* bs[6] = { k1b, q1b, v1b, k2b, q2b, v2b };
    int idx = blockIdx.x * 256 + threadIdx.x;        // [0, 2*33*512)
    if (idx < 2 * 33 * D_) {
        int ph = idx / (33 * D_);
        int rem = idx - ph * 33 * D_;
        int o = rem / D_, c = rem % D_;
        int mtx = ph * 3 + o / 11, h = o % 11;
        g_wt[idx] = ws[mtx][c * H_ + h];
    }
    if (idx < 66) {
        int ph = idx / 33, o = idx % 33;
        g_wb[idx] = bs[ph * 3 + o / 11][o % 11];
    }
}

// ---------------- 1) embedding + positional encoding ----------------
__global__ void embed_kernel(const int* __restrict__ x, const float* __restrict__ tab) {
    int idx = blockIdx.x * 256 + threadIdx.x;
    int d  = idx & (D_ - 1);
    int rs = idx >> 9;
    int s  = rs & (S_ - 1);
    int tok = x[rs];
    int e = d & ~1;
    float ang = (float)s * expf(-(float)e * (9.210340371976184f / 256.0f));
    float p = (d & 1) ? cosf(ang) : sinf(ang);
    g_emb[idx] = tab[(size_t)tok * D_ + d] + p;
}

// ---------------- 2) q/k/v projections: warp-per-row, coalesced Wt reads ----------------
__global__ void qkv_kernel(int phase) {
    const float* src = phase ? g_h1 : g_emb;
    __shared__ float Esh[8 * D_];
    int r0 = blockIdx.x * 8;
    int tid = threadIdx.x;
    {
        const float4* s4 = (const float4*)(src + (size_t)r0 * D_);
        float4* e4 = (float4*)Esh;
        #pragma unroll
        for (int i = 0; i < 4; i++) e4[tid + i * 256] = s4[tid + i * 256];
    }
    __syncthreads();

    int w = tid >> 5, lane = tid & 31;               // warp = row
    float4 e[4];
    #pragma unroll
    for (int j = 0; j < 4; j++) e[j] = ((const float4*)&Esh[w * D_])[lane + 32 * j];

    const float* wt = g_wt + phase * 33 * D_;
    const float* wb = g_wb + phase * 33;
    int row = r0 + w;
    #pragma unroll 3
    for (int o = 0; o < 33; o++) {
        const float4* w4 = (const float4*)&wt[o * D_];
        float s = 0.f;
        #pragma unroll
        for (int j = 0; j < 4; j++) {
            float4 wv = w4[lane + 32 * j];           // coalesced 128B per j
            s += e[j].x * wv.x + e[j].y * wv.y + e[j].z * wv.z + e[j].w * wv.w;
        }
        #pragma unroll
        for (int off = 16; off > 0; off >>= 1) s += __shfl_xor_sync(0xFFFFFFFFu, s, off);
        if (lane == 0) {
            float* dst = (o < 11) ? g_k : (o < 22) ? g_q : g_v;
            dst[row * HP + (o % 11)] = s + wb[o];
        }
    }
}

// ---------------- 3) scores + causal mask + softmax over QUERY axis ----------------
// float4 Q/K loads (pad lane zero => exact), R11 smem-tree reductions.
__global__ void scores_kernel() {
    int k = blockIdx.x, b = blockIdx.y;
    int tid = threadIdx.x;
    __shared__ float4 kvs[3];
    __shared__ float red[256];
    if (tid < 3) kvs[tid] = ((const float4*)&g_k[(b * S_ + k) * HP])[tid];
    __syncthreads();
    float4 k0 = kvs[0], k1 = kvs[1], k2 = kvs[2];

    float dloc[8];
    float m = -1e30f;
    int cnt = 0;
    for (int q = k + tid; q < S_; q += 256) {
        const float4* qp = (const float4*)&g_q[(b * S_ + q) * HP];
        float4 t = qp[0];
        float d = t.x * k0.x + t.y * k0.y + t.z * k0.z + t.w * k0.w;
        t = qp[1];
        d += t.x * k1.x + t.y * k1.y + t.z * k1.z + t.w * k1.w;
        t = qp[2];
        d += t.x * k2.x + t.y * k2.y + t.z * k2.z + t.w * k2.w;
        dloc[cnt++] = d;
        m = fmaxf(m, d);
    }
    red[tid] = m; __syncthreads();
    #pragma unroll
    for (int s = 128; s > 0; s >>= 1) {
        if (tid < s) red[tid] = fmaxf(red[tid], red[tid + s]);
        __syncthreads();
    }
    float M = red[0]; __syncthreads();

    float ssum = 0.f;
    for (int i = 0; i < cnt; i++) { dloc[i] = expf(dloc[i] - M); ssum += dloc[i]; }
    red[tid] = ssum; __syncthreads();
    #pragma unroll
    for (int s = 128; s > 0; s >>= 1) {
        if (tid < s) red[tid] += red[tid + s];
        __syncthreads();
    }
    float inv = 1.0f / red[0];

    size_t rowbase = ((size_t)b * S_ + k) * S_;
    cnt = 0;
    for (int q = k + tid; q < S_; q += 256) g_att[rowbase + q] = dloc[cnt++] * inv;
    for (int q = tid; q < k; q += 256)      g_att[rowbase + q] = 0.f;
}

// ---------------- 4) res = att @ v  (float4 V path; pad lane zero => exact) ----------
__global__ void attv_kernel() {
    int qt = blockIdx.x, kc = blockIdx.y, b = blockIdx.z;
    int tid = threadIdx.x;
    int q = qt * 128 + tid;
    float4* dst4 = (float4*)&g_part[((kc * R_) + b * S_ + q) * HP];
    if (kc > qt) {                       // fully masked chunk
        float4 z = {0.f, 0.f, 0.f, 0.f};
        dst4[0] = z; dst4[1] = z; dst4[2] = z;
        return;
    }
    __shared__ float4 vsh4[128 * 3];
    int k0 = kc * 128;
    const float4* vb4 = (const float4*)&g_v[(b * S_ + k0) * HP];
    #pragma unroll
    for (int i = 0; i < 3; i++) vsh4[tid + i * 128] = vb4[tid + i * 128];
    __syncthreads();

    float4 a0 = {0.f, 0.f, 0.f, 0.f}, a1 = a0, a2 = a0;
    size_t attbase = ((size_t)b * S_ + k0) * S_ + q;
    #pragma unroll 4
    for (int kk = 0; kk < 128; kk++) {
        float a = g_att[attbase + (size_t)kk * S_];
        float4 v0 = vsh4[kk * 3], v1 = vsh4[kk * 3 + 1], v2 = vsh4[kk * 3 + 2];
        a0.x += a * v0.x; a0.y += a * v0.y; a0.z += a * v0.z; a0.w += a * v0.w;
        a1.x += a * v1.x; a1.y += a * v1.y; a1.z += a * v1.z; a1.w += a * v1.w;
        a2.x += a * v2.x; a2.y += a * v2.y; a2.z += a * v2.z; a2.w += a * v2.w;
    }
    dst4[0] = a0; dst4[1] = a1; dst4[2] = a2;
}

// ---------------- 4b) sum partials ----------------
__global__ void reduce_part_kernel() {
    int idx = blockIdx.x * 256 + threadIdx.x;        // [0, R_*HP)
    float s = 0.f;
    #pragma unroll
    for (int p = 0; p < KCH; p++) s += g_part[p * R_ * HP + idx];
    g_res[idx] = s;
}

// ---------------- 5) out = res @ fw + fb ----------------
// phase 0: fp32 to g_h1. phase 1: fp16 (x A_SCALE) into tiled GEMM-A layout.
__global__ void ff_kernel(int phase, const float* __restrict__ fw, const float* __restrict__ fb) {
    int idx = blockIdx.x * 256 + threadIdx.x;
    int r = idx >> 9, d = idx & (D_ - 1);
    float sacc = fb[d];
    #pragma unroll
    for (int h = 0; h < H_; h++) sacc += g_res[r * HP + h] * fw[h * D_ + d];
    if (phase == 0) {
        g_h1[idx] = sacc;
    } else {
        int mt = r >> 7, rrow = r & 127, kc = d >> 5, kk = d & 31;
        size_t off = (((size_t)(mt * NKC + kc) * 128) + rrow) * LDP + kk;
        ((__half*)g_a_hi4)[off] = __float2half(sacc * A_SCALE);
    }
}

// ---------------- 6a) transpose out_w -> tiled fp16 GEMM-B layout ----------------
__global__ void conv_b_kernel(const float* __restrict__ outw) {
    __shared__ float t[32][33];
    int v0 = blockIdx.x * 32, k0 = blockIdx.y * 32;
    int tx = threadIdx.x, ty = threadIdx.y;          // 32 x 8
    #pragma unroll
    for (int j = 0; j < 4; j++) {
        int k = k0 + ty + j * 8;
        t[ty + j * 8][tx] = outw[(size_t)k * V_ + v0 + tx];
    }
    __syncthreads();
    int kc = k0 >> 5;
    #pragma unroll
    for (int j = 0; j < 4; j++) {
        int v = v0 + ty + j * 8;
        float val = t[tx][ty + j * 8] * B_SCALE;     // = outw[k0+tx][v] * 2^6
        int nt = v >> 8, vrow = v & 255;
        size_t off = (((size_t)(nt * NKC + kc) * 256) + vrow) * LDP + tx;
        ((__half*)g_bt_hi4)[off] = __float2half(val);
    }
}

// ---------------- 6b) bulk-copy pipelined fp16 MMA GEMM ----------------
#define B_HI_O TILE_A_BYTES                  // 10240
#define STG_SZ (TILE_A_BYTES + TILE_B_BYTES) // 30720
#define NSTAGE 4
#define CTRL 1024
#define GSMEM (CTRL + NSTAGE * STG_SZ)       // 123904

__device__ __forceinline__ uint32_t smem_u32(const void* p) {
    uint32_t r;
    asm("{ .reg .u64 t; cvta.to.shared.u64 t, %1; cvt.u32.u64 %0, t; }"
        : "=r"(r) : "l"(p));
    return r;
}
__device__ __forceinline__ void bulk_g2s(uint32_t dst, const void* src, uint32_t bytes,
                                         uint32_t mbar) {
    asm volatile(
        "cp.async.bulk.shared::cluster.global.mbarrier::complete_tx::bytes [%0], [%1], %2, [%3];"
        :: "r"(dst), "l"(src), "r"(bytes), "r"(mbar) : "memory");
}
__device__ __forceinline__ void mbar_expect(uint32_t mbar, uint32_t bytes) {
    asm volatile("mbarrier.arrive.expect_tx.shared.b64 _, [%0], %1;"
                 :: "r"(mbar), "r"(bytes) : "memory");
}
__device__ __forceinline__ void mbar_wait(uint32_t addr, uint32_t parity) {
    asm volatile(
        "{\n\t.reg .pred P;\n\t"
        "W_%=:\n\t"
        "mbarrier.try_wait.parity.acquire.cta.shared::cta.b64 P, [%0], %1, 0x989680;\n\t"
        "@P bra.uni D_%=;\n\t"
        "bra.uni W_%=;\n\t"
        "D_%=:\n\t}"
        :: "r"(addr), "r"(parity) : "memory");
}
__device__ __forceinline__ void ldmatrix4(uint32_t* r, uint32_t addr) {
    asm volatile("ldmatrix.sync.aligned.m8n8.x4.shared.b16 {%0,%1,%2,%3}, [%4];"
                 : "=r"(r[0]), "=r"(r[1]), "=r"(r[2]), "=r"(r[3]) : "r"(addr));
}
__device__ __forceinline__ void mma16816(float* c, const uint32_t* a, uint32_t b0, uint32_t b1) {
    asm volatile(
        "mma.sync.aligned.m16n8k16.row.col.f32.f16.f16.f32 "
        "{%0,%1,%2,%3}, {%4,%5,%6,%7}, {%8,%9}, {%0,%1,%2,%3};"
        : "+f"(c[0]), "+f"(c[1]), "+f"(c[2]), "+f"(c[3])
        : "r"(a[0]), "r"(a[1]), "r"(a[2]), "r"(a[3]), "r"(b0), "r"(b1));
}

__global__ __launch_bounds__(256, 1)
void gemm_mma_kernel(const float* __restrict__ bias, float* __restrict__ C) {
    extern __shared__ __align__(16) char smem[];
    uint32_t sb = smem_u32(smem);
    int tid = threadIdx.x;
    int wid = tid >> 5, lid = tid & 31;
    int rowBase = blockIdx.x * 128;
    int colBase = blockIdx.y * 256;

    const char* gAh = (const char*)g_a_hi4 + (size_t)blockIdx.x * NKC * TILE_A_BYTES;
    const char* gBh = (const char*)g_bt_hi4 + (size_t)blockIdx.y * NKC * TILE_B_BYTES;

    if (tid == 0) {
        #pragma unroll
        for (int s = 0; s < NSTAGE; s++)
            asm volatile("mbarrier.init.shared.b64 [%0], 1;" :: "r"(sb + 8u * s) : "memory");
    }
    __syncthreads();

    auto issue = [&](int c, int s) {
        uint32_t mb = sb + 8u * s;
        uint32_t stg = sb + CTRL + (uint32_t)s * STG_SZ;
        mbar_expect(mb, STG_SZ);
        bulk_g2s(stg, gAh + (size_t)c * TILE_A_BYTES, TILE_A_BYTES, mb);
        bulk_g2s(stg + B_HI_O,                    gBh + (size_t)c * TILE_B_BYTES, TILE_B_BYTES / 2, mb);
        bulk_g2s(stg + B_HI_O + TILE_B_BYTES / 2, gBh + (size_t)c * TILE_B_BYTES + TILE_B_BYTES / 2, TILE_B_BYTES / 2, mb);
    };

    if (tid == 0) { issue(0, 0); issue(1, 1); issue(2, 2); issue(3, 3); }

    int warpM = (wid & 1) * 64;       // 2 m-warps
    int warpN = (wid >> 1) * 64;      // 4 n-warps
    int lrow = lid & 15;
    int lk = (lid >> 4) * 8;

    float acc[4][8][4];
    #pragma unroll
    for (int i = 0; i < 4; i++)
        #pragma unroll
        for (int j = 0; j < 8; j++)
            #pragma unroll
            for (int v = 0; v < 4; v++) acc[i][j][v] = 0.f;

    #pragma unroll 1
    for (int c = 0; c < NKC; c++) {
        int s = c % NSTAGE;
        mbar_wait(sb + 8u * s, (c / NSTAGE) & 1);
        uint32_t stg = sb + CTRL + (uint32_t)s * STG_SZ;

        #pragma unroll
        for (int k16 = 0; k16 < 2; k16++) {
            uint32_t a[4][4];
            #pragma unroll
            for (int mi = 0; mi < 4; mi++)
                ldmatrix4(a[mi], stg + ((warpM + mi * 16 + lrow) * LDP + k16 * 16 + lk) * 2);
            uint32_t b[4][4];
            #pragma unroll
            for (int ni = 0; ni < 4; ni++)
                ldmatrix4(b[ni], stg + B_HI_O + ((warpN + ni * 16 + lrow) * LDP + k16 * 16 + lk) * 2);
            #pragma unroll
            for (int mi = 0; mi < 4; mi++)
                #pragma unroll
                for (int nj = 0; nj < 8; nj++) {
                    uint32_t b0 = (nj & 1) ? b[nj >> 1][1] : b[nj >> 1][0];
                    uint32_t b1 = (nj & 1) ? b[nj >> 1][3] : b[nj >> 1][2];
                    mma16816(acc[mi][nj], a[mi], b0, b1);
                }
        }
        __syncthreads();
        if (tid == 0 && c + NSTAGE < NKC) issue(c + NSTAGE, s);
    }

    // ---- epilogue: unscale + bias, direct stores ----
    int g = lid >> 2, tig = lid & 3;
    #pragma unroll
    for (int mi = 0; mi < 4; mi++) {
        #pragma unroll
        for (int nj = 0; nj < 8; nj++) {
            int row = rowBase + warpM + mi * 16 + g;
            int col = colBase + warpN + nj * 8 + tig * 2;
            float2 bv = *(const float2*)&bias[col];
            float2 o0 = { acc[mi][nj][0] * OUT_SCALE + bv.x, acc[mi][nj][1] * OUT_SCALE + bv.y };
            float2 o1 = { acc[mi][nj][2] * OUT_SCALE + bv.x, acc[mi][nj][3] * OUT_SCALE + bv.y };
            *(float2*)&C[(size_t)row * V_ + col] = o0;
            *(float2*)&C[(size_t)(row + 8) * V_ + col] = o1;
        }
    }
}

// ---------------- launch ----------------
extern "C" void kernel_launch(void* const* d_in, const int* in_sizes, int n_in,
                              void* d_out, int out_size) {
    const int*   x    = (const int*)d_in[0];
    const float* tab  = (const float*)d_in[1];
    const float* k1w  = (const float*)d_in[2];
    const float* k1b  = (const float*)d_in[3];
    const float* q1w  = (const float*)d_in[4];
    const float* q1b  = (const float*)d_in[5];
    const float* v1w  = (const float*)d_in[6];
    const float* v1b  = (const float*)d_in[7];
    const float* f1w  = (const float*)d_in[8];
    const float* f1b  = (const float*)d_in[9];
    const float* k2w  = (const float*)d_in[10];
    const float* k2b  = (const float*)d_in[11];
    const float* q2w  = (const float*)d_in[12];
    const float* q2b  = (const float*)d_in[13];
    const float* v2w  = (const float*)d_in[14];
    const float* v2b  = (const float*)d_in[15];
    const float* f2w  = (const float*)d_in[16];
    const float* f2b  = (const float*)d_in[17];
    const float* outw = (const float*)d_in[18];
    const float* outb = (const float*)d_in[19];
    float* out = (float*)d_out;

    cudaFuncSetAttribute(gemm_mma_kernel, cudaFuncAttributeMaxDynamicSharedMemorySize, GSMEM);

    // weight prep (independent of activations)
    prep_wt_kernel<<<(2 * 33 * D_ + 255) / 256, 256>>>(k1w, q1w, v1w, k2w, q2w, v2w,
                                                        k1b, q1b, v1b, k2b, q2b, v2b);
    conv_b_kernel<<<dim3(V_ / 32, D_ / 32), dim3(32, 8)>>>(outw);

    embed_kernel<<<(R_ * D_) / 256, 256>>>(x, tab);

    // attention block 1: g_emb -> g_h1
    qkv_kernel<<<R_ / 8, 256>>>(0);
    scores_kernel<<<dim3(S_, B_), 256>>>();
    attv_kernel<<<dim3(16, KCH, 2), 128>>>();
    reduce_part_kernel<<<(R_ * HP) / 256, 256>>>();
    ff_kernel<<<(R_ * D_) / 256, 256>>>(0, f1w, f1b);

    // attention block 2: g_h1 -> tiled fp16 (fused in ff phase 1)
    qkv_kernel<<<R_ / 8, 256>>>(1);
    scores_kernel<<<dim3(S_, B_), 256>>>();
    attv_kernel<<<dim3(16, KCH, 2), 128>>>();
    reduce_part_kernel<<<(R_ * HP) / 256, 256>>>();
    ff_kernel<<<(R_ * D_) / 256, 256>>>(1, f2w, f2b);

    // final vocab projection: bulk-fed fp16 tensor-core GEMM
    gemm_mma_kernel<<<dim3(MT_, NT_), 256, GSMEM>>>(outb, out);
}